// round 17
// baseline (speedup 1.0000x reference)
#include <cuda_runtime.h>
#include <cuda_fp16.h>
#include <cstdint>
#include <cmath>

// Problem constants
#define TT 100
#define BB 1000
#define EE 512
#define DD 256
#define LL 4
#define MROWS (TT*BB)          // 100000

// ---------------- scratch (static device memory; no allocations) ----------------
__device__ __half g_xl[(size_t)MROWS * EE];    // LN output / head hidden (fp16)
__device__ __half g_U [(size_t)MROWS * 2048];  // projected gates (fp16, gate-interleaved)
__device__ __half g_x [(size_t)MROWS * EE];    // layer activations (fp16)
__device__ __half g_Wr [(size_t)LL * 2 * 1024 * EE]; // transposed+rounded sru_W: [l,d][n',k], n'=dd*4+gate
__device__ __half g_W1r[(size_t)EE * EE];            // transposed+rounded W1: [n,k]

// ---------------- helpers ----------------
__device__ __forceinline__ uint32_t su32(const void* p) {
    return (uint32_t)__cvta_generic_to_shared(p);
}

__device__ __forceinline__ void cp16(uint32_t dst, const void* src, int sz) {
    asm volatile("cp.async.ca.shared.global [%0], [%1], 16, %2;" :: "r"(dst), "l"(src), "r"(sz));
}

__device__ __forceinline__ void mma_f16(float c[4], const uint32_t a[4], const uint32_t b[2]) {
    asm volatile(
        "mma.sync.aligned.m16n8k16.row.col.f32.f16.f16.f32 "
        "{%0,%1,%2,%3}, {%4,%5,%6,%7}, {%8,%9}, {%0,%1,%2,%3};\n"
        : "+f"(c[0]), "+f"(c[1]), "+f"(c[2]), "+f"(c[3])
        : "r"(a[0]), "r"(a[1]), "r"(a[2]), "r"(a[3]), "r"(b[0]), "r"(b[1]));
}

__device__ __forceinline__ void ldsm4(uint32_t& r0, uint32_t& r1, uint32_t& r2, uint32_t& r3,
                                      uint32_t addr) {
    asm volatile("ldmatrix.sync.aligned.m8n8.x4.shared.b16 {%0,%1,%2,%3}, [%4];"
                 : "=r"(r0), "=r"(r1), "=r"(r2), "=r"(r3) : "r"(addr));
}

// ---------------- transpose + fp16 round: [K,N] -> [N,K] per batch ----------------
// perm=1: output row n' = (n&255)*4 + (n>>8)  (gate-interleave within 1024-col dir block)
__global__ void __launch_bounds__(256) transpose_half(
    const float* __restrict__ in, __half* __restrict__ out, int K, int N, int perm)
{
    __shared__ float tile[32][33];
    int b = blockIdx.z;
    const float* ip = in + (size_t)b * K * N;
    __half* op = out + (size_t)b * K * N;
    int k0 = blockIdx.y * 32, n0 = blockIdx.x * 32;
    int tx = threadIdx.x & 31, ty = threadIdx.x >> 5;  // 32x8
#pragma unroll
    for (int i = 0; i < 32; i += 8)
        tile[ty + i][tx] = ip[(size_t)(k0 + ty + i) * N + n0 + tx];
    __syncthreads();
#pragma unroll
    for (int i = 0; i < 32; i += 8) {
        int n = n0 + ty + i;
        int nw = perm ? ((n & 255) * 4 + (n >> 8)) : n;
        op[(size_t)nw * K + k0 + tx] = __float2half_rn(tile[tx][ty + i]);
    }
}

// ---------------- LayerNorm (fp32 input, fp16 output): one warp per token ----------------
__global__ void __launch_bounds__(256) ln_f32(
    const float* __restrict__ x, const float* __restrict__ g,
    const float* __restrict__ b, __half* __restrict__ out, int Mrows)
{
    int warp = (blockIdx.x * blockDim.x + threadIdx.x) >> 5;
    int lane = threadIdx.x & 31;
    if (warp >= Mrows) return;

    const float4* xr = (const float4*)(x + (size_t)warp * EE);
    float4 v[4];
    float s = 0.f, sq = 0.f;
#pragma unroll
    for (int j = 0; j < 4; j++) {
        v[j] = xr[lane + j * 32];
        s  += v[j].x + v[j].y + v[j].z + v[j].w;
        sq += v[j].x*v[j].x + v[j].y*v[j].y + v[j].z*v[j].z + v[j].w*v[j].w;
    }
#pragma unroll
    for (int o = 16; o > 0; o >>= 1) {
        s  += __shfl_xor_sync(0xffffffffu, s, o);
        sq += __shfl_xor_sync(0xffffffffu, sq, o);
    }
    float mean = s * (1.f / EE);
    float var  = sq * (1.f / EE) - mean * mean;
    float rstd = rsqrtf(var + 1e-5f);

    __half2* orow = (__half2*)(out + (size_t)warp * EE);
    const float4* gg4 = (const float4*)g;
    const float4* bb4 = (const float4*)b;
#pragma unroll
    for (int j = 0; j < 4; j++) {
        int e4 = lane + j * 32;
        float4 gg = gg4[e4], bb = bb4[e4];
        float w0 = (v[j].x - mean) * rstd * gg.x + bb.x;
        float w1 = (v[j].y - mean) * rstd * gg.y + bb.y;
        float w2 = (v[j].z - mean) * rstd * gg.z + bb.z;
        float w3 = (v[j].w - mean) * rstd * gg.w + bb.w;
        orow[e4 * 2 + 0] = __floats2half2_rn(w0, w1);
        orow[e4 * 2 + 1] = __floats2half2_rn(w2, w3);
    }
}

// ---------------- LayerNorm (fp16 input, fp16 output) ----------------
__global__ void __launch_bounds__(256) ln_f16(
    const __half* __restrict__ x, const float* __restrict__ g,
    const float* __restrict__ b, __half* __restrict__ out, int Mrows)
{
    int warp = (blockIdx.x * blockDim.x + threadIdx.x) >> 5;
    int lane = threadIdx.x & 31;
    if (warp >= Mrows) return;

    const uint4* xr = (const uint4*)(x + (size_t)warp * EE);  // 8 halves per uint4
    uint4 v[2];
    float f[16];
    float s = 0.f, sq = 0.f;
#pragma unroll
    for (int j = 0; j < 2; j++) {
        v[j] = xr[lane + j * 32];
        const __half2* h2 = (const __half2*)&v[j];
#pragma unroll
        for (int q = 0; q < 4; q++) {
            float2 p = __half22float2(h2[q]);
            f[j * 8 + q * 2 + 0] = p.x;
            f[j * 8 + q * 2 + 1] = p.y;
            s += p.x + p.y;
            sq += p.x * p.x + p.y * p.y;
        }
    }
#pragma unroll
    for (int o = 16; o > 0; o >>= 1) {
        s  += __shfl_xor_sync(0xffffffffu, s, o);
        sq += __shfl_xor_sync(0xffffffffu, sq, o);
    }
    float mean = s * (1.f / EE);
    float var  = sq * (1.f / EE) - mean * mean;
    float rstd = rsqrtf(var + 1e-5f);

    uint4* orow = (uint4*)(out + (size_t)warp * EE);
#pragma unroll
    for (int j = 0; j < 2; j++) {
        int e0 = (lane + j * 32) * 8;
        uint4 w;
        __half2* wh = (__half2*)&w;
        const float4* gp = (const float4*)(g + e0);
        const float4* bp4 = (const float4*)(b + e0);
#pragma unroll
        for (int h = 0; h < 2; h++) {
            float4 gg = gp[h], bb = bp4[h];
            int fi = j * 8 + h * 4;
            float a0 = (f[fi + 0] - mean) * rstd * gg.x + bb.x;
            float a1 = (f[fi + 1] - mean) * rstd * gg.y + bb.y;
            float a2 = (f[fi + 2] - mean) * rstd * gg.z + bb.z;
            float a3 = (f[fi + 3] - mean) * rstd * gg.w + bb.w;
            wh[h * 2 + 0] = __floats2half2_rn(a0, a1);
            wh[h * 2 + 1] = __floats2half2_rn(a2, a3);
        }
        orow[lane + j * 32] = w;
    }
}

// ---------------- fp16 GEMM: C[M,N] = A[M,512] * Bt[N,512]^T, mma.sync m16n8k16 ----------------
// Tile 128x128x32, 128-thread CTA (2x2 warps, warp tile 64x64), 2 CTAs/SM.
// 6-stage cp.async pipeline, ONE barrier per 2 chunks, fragment double-buffering.
// SW64-swizzled 64B rows: 16B chunk c stored at c ^ ((row>>1)&3).
#define BM 128
#define BN 128
#define BK 32
#define A_BYT (BM*64)                // 8192
#define B_BYT (BN*64)                // 8192
#define STG_BYT (A_BYT + B_BYT)      // 16384
#define NSTG 6
#define GEMM_SMEM (NSTG*STG_BYT + 128)

__global__ void __launch_bounds__(128, 2) gemm_fp16(
    const __half* __restrict__ A, const __half* __restrict__ Bt,
    const float* __restrict__ bias, __half* __restrict__ C,
    int Mrows, int Ncols, int dlog2, long long dstride)
{
    extern __shared__ __half smh[];
    const uint32_t ub = (su32(smh) + 127u) & ~127u;   // 128B-aligned smem base

    const int tid  = threadIdx.x;
    const int warp = tid >> 5, lane = tid & 31;
    const int g = lane >> 2, t = lane & 3;
    const int wm0 = (warp >> 1) * 64;   // 2 warps along M
    const int wn0 = (warp & 1) * 64;    // 2 warps along N
    const int m0 = blockIdx.y * BM;
    const int n0 = blockIdx.x * BN;
    const int dir = n0 >> dlog2;
    const int ncb = n0 & ((1 << dlog2) - 1);
    const __half* Bbase = Bt + (size_t)dir * dstride + (size_t)ncb * EE;

    // fill coords: row = tid>>2 (+32 per pass), swizzled 16B chunk
    const int frow = tid >> 2;
    const uint32_t fsw16 = (uint32_t)(((tid & 3) ^ ((frow >> 1) & 3)) * 16);
    const int fcol = (tid & 3) * 8;    // source col in halves

    // ldmatrix per-lane swizzled byte offsets (kk=0); kk=16 -> XOR 32
    const int ar = lane & 15;
    const uint32_t a_lane = (uint32_t)(ar * 64 + (((lane >> 4) ^ ((ar >> 1) & 3)) * 16));
    const int br = (lane & 7) | (((lane >> 4) & 1) << 3);
    const uint32_t b_lane = (uint32_t)(br * 64 + ((((lane >> 3) & 1) ^ ((br >> 1) & 3)) * 16));

    float acc[4][8][4];
#pragma unroll
    for (int i = 0; i < 4; i++)
#pragma unroll
        for (int j = 0; j < 8; j++)
#pragma unroll
            for (int k = 0; k < 4; k++) acc[i][j][k] = 0.f;

    auto fill = [&](int kt, int s) {
        uint32_t Ast = ub + s * STG_BYT;
        uint32_t Bst = Ast + A_BYT;
        const int k0 = kt * BK + fcol;
#pragma unroll
        for (int i = 0; i < 4; i++) {
            int r = frow + i * 32;
            int m = m0 + r;
            bool ok = (m < Mrows);
            cp16(Ast + (uint32_t)(r * 64) + fsw16,
                 A + (size_t)(ok ? m : 0) * EE + k0, ok ? 16 : 0);
        }
#pragma unroll
        for (int i = 0; i < 4; i++) {
            int r = frow + i * 32;
            cp16(Bst + (uint32_t)(r * 64) + fsw16, Bbase + (size_t)r * EE + k0, 16);
        }
    };

    // fragment double buffers
    uint32_t afA[4][4], bfA[8][2], afB[4][4], bfB[8][2];

    auto ldsm_frags = [&](int s, int ks, uint32_t af[4][4], uint32_t bf[8][2]) {
        const uint32_t kx = ks ? 32u : 0u;
        const uint32_t a_base = ub + s * STG_BYT + a_lane;
        const uint32_t b_base = ub + s * STG_BYT + A_BYT + b_lane;
#pragma unroll
        for (int i = 0; i < 4; i++)
            ldsm4(af[i][0], af[i][1], af[i][2], af[i][3],
                  (a_base + (uint32_t)((wm0 + i * 16) * 64)) ^ kx);
#pragma unroll
        for (int jp = 0; jp < 4; jp++) {
            int j = jp * 2;
            ldsm4(bf[j][0], bf[j][1], bf[j + 1][0], bf[j + 1][1],
                  (b_base + (uint32_t)((wn0 + j * 8) * 64)) ^ kx);
        }
    };

    auto do_mma = [&](uint32_t af[4][4], uint32_t bf[8][2]) {
#pragma unroll
        for (int i = 0; i < 4; i++)
#pragma unroll
            for (int j = 0; j < 8; j++)
                mma_f16(acc[i][j], af[i], bf[j]);
    };

    const int NKT = EE / BK;  // 16

    // prologue: 2 fill-pairs (stages 0-3)
    fill(0, 0); fill(1, 1); asm volatile("cp.async.commit_group;");
    fill(2, 2); fill(3, 3); asm volatile("cp.async.commit_group;");
    asm volatile("cp.async.wait_group 1;");   // stages 0,1 ready
    __syncthreads();
    ldsm_frags(0, 0, afA, bfA);

    // iteration p handles chunks p, p+1; invariant entering: stages p,p+1 ready,
    // outstanding groups = {G(p+2,p+3)}; afA holds chunk-p ks0 frags.
#pragma unroll 1
    for (int p = 0; p < NKT; p += 2) {
        const int s0 = p % NSTG, s1 = (p + 1) % NSTG;
        // fill stages p+4,p+5 (free: last read in chunks p-2/p-1, before previous sync)
        if (p + 4 < NKT) { fill(p + 4, (p + 4) % NSTG); fill(p + 5, (p + 5) % NSTG); }
        asm volatile("cp.async.commit_group;");
        // chunk p
        ldsm_frags(s0, 1, afB, bfB);
        do_mma(afA, bfA);
        ldsm_frags(s1, 0, afA, bfA);
        do_mma(afB, bfB);
        // chunk p+1
        ldsm_frags(s1, 1, afB, bfB);
        do_mma(afA, bfA);
        // advance: need stages p+2,p+3 complete; newest fill group may stay pending
        asm volatile("cp.async.wait_group 1;");
        __syncthreads();
        if (p + 2 < NKT) ldsm_frags((p + 2) % NSTG, 0, afA, bfA);
        do_mma(afB, bfB);
    }

    // epilogue: fp32 acc (+bias) -> fp16 stores
#pragma unroll
    for (int i = 0; i < 4; i++) {
        int r0 = m0 + wm0 + i * 16 + g;
        int r1 = r0 + 8;
#pragma unroll
        for (int j = 0; j < 8; j++) {
            int cc = n0 + wn0 + j * 8 + 2 * t;
            float b0v = 0.f, b1v = 0.f;
            if (bias) { b0v = bias[cc]; b1v = bias[cc + 1]; }
            if (r0 < Mrows)
                *(__half2*)(C + (size_t)r0 * Ncols + cc) =
                    __floats2half2_rn(acc[i][j][0] + b0v, acc[i][j][1] + b1v);
            if (r1 < Mrows)
                *(__half2*)(C + (size_t)r1 * Ncols + cc) =
                    __floats2half2_rn(acc[i][j][2] + b0v, acc[i][j][3] + b1v);
        }
    }
}

// ---------------- SRU elementwise scan: gate-interleaved U, next-step prefetch ----------------
__global__ void __launch_bounds__(256) sru_scan(
    const __half* __restrict__ U, const float* __restrict__ v,
    const float* __restrict__ bp, __half* __restrict__ X)
{
    int tid = blockIdx.x * blockDim.x + threadIdx.x;
    if (tid >= 2 * BB * DD) return;
    int dir = tid / (BB * DD);
    int rem = tid - dir * (BB * DD);
    int b = rem / DD;
    int dd = rem - b * DD;

    float vf = v[dir * 2 * DD + dd];
    float vr = v[dir * 2 * DD + DD + dd];
    float bf = bp[dir * 2 * DD + dd];
    float br = bp[dir * 2 * DD + DD + dd];

    const size_t colU = (size_t)dir * 1024 + (size_t)dd * 4;  // gate-interleaved
    const size_t colX = (size_t)dir * DD + dd;

    float c = 0.f;
    int t0 = dir ? (TT - 1) : 0;
    uint2 raw = *(const uint2*)(U + ((size_t)t0 * BB + b) * 2048 + colU);
    for (int s = 0; s < TT; s++) {
        int t = dir ? (TT - 1 - s) : s;
        uint2 cur = raw;
        if (s + 1 < TT) {
            int tn = dir ? (TT - 2 - s) : (s + 1);
            raw = *(const uint2*)(U + ((size_t)tn * BB + b) * 2048 + colU);
        }
        float2 p0 = __half22float2(*(const __half2*)&cur.x);
        float2 p1 = __half22float2(*(const __half2*)&cur.y);
        float u0 = p0.x, u1 = p0.y, u2 = p1.x, u3 = p1.y;
        float f = 1.f / (1.f + expf(-(u1 + vf * c + bf)));
        c = f * c + (1.f - f) * u0;
        float r = 1.f / (1.f + expf(-(u2 + vr * c + br)));
        X[((size_t)t * BB + b) * EE + colX] = __float2half_rn(r * c + (1.f - r) * u3);
    }
}

// ---------------- head: BN(eval) + relu + W2 (512x4) + log_softmax; one warp per token ----------------
__global__ void __launch_bounds__(256) head_kernel(
    const __half* __restrict__ h,
    const float* __restrict__ bn_g, const float* __restrict__ bn_b,
    const float* __restrict__ bn_mean, const float* __restrict__ bn_var,
    const float* __restrict__ W2, const float* __restrict__ b2,
    float* __restrict__ out, int Mrows)
{
    __shared__ float w2s[EE * 4];
    __shared__ float scs[EE], tbs[EE];
    __shared__ float b2s[4];
    int tid = threadIdx.x;
    for (int i = tid; i < EE * 4; i += 256) w2s[i] = W2[i];
    for (int i = tid; i < EE; i += 256) {
        float s = bn_g[i] * rsqrtf(bn_var[i] + 1e-5f);
        scs[i] = s;
        tbs[i] = bn_b[i] - bn_mean[i] * s;
    }
    if (tid < 4) b2s[tid] = b2[tid];
    __syncthreads();

    int warp = (blockIdx.x * blockDim.x + tid) >> 5;
    int lane = tid & 31;
    if (warp >= Mrows) return;

    const uint4* hr = (const uint4*)(h + (size_t)warp * EE);  // 8 halves per uint4
    float a0 = 0.f, a1 = 0.f, a2 = 0.f, a3 = 0.f;
#pragma unroll
    for (int j = 0; j < 2; j++) {
        uint4 hv = hr[lane + j * 32];
        const __half2* h2 = (const __half2*)&hv;
        int e0 = (lane + j * 32) * 8;
#pragma unroll
        for (int q = 0; q < 4; q++) {
            float2 p = __half22float2(h2[q]);
            int e = e0 + q * 2;
            float v0 = fmaxf(p.x * scs[e]     + tbs[e],     0.f);
            float v1 = fmaxf(p.y * scs[e + 1] + tbs[e + 1], 0.f);
            a0 += v0 * w2s[e * 4 + 0] + v1 * w2s[(e + 1) * 4 + 0];
            a1 += v0 * w2s[e * 4 + 1] + v1 * w2s[(e + 1) * 4 + 1];
            a2 += v0 * w2s[e * 4 + 2] + v1 * w2s[(e + 1) * 4 + 2];
            a3 += v0 * w2s[e * 4 + 3] + v1 * w2s[(e + 1) * 4 + 3];
        }
    }
#pragma unroll
    for (int o = 16; o > 0; o >>= 1) {
        a0 += __shfl_xor_sync(0xffffffffu, a0, o);
        a1 += __shfl_xor_sync(0xffffffffu, a1, o);
        a2 += __shfl_xor_sync(0xffffffffu, a2, o);
        a3 += __shfl_xor_sync(0xffffffffu, a3, o);
    }
    if (lane == 0) {
        float l0 = a0 + b2s[0], l1 = a1 + b2s[1], l2 = a2 + b2s[2], l3 = a3 + b2s[3];
        float m = fmaxf(fmaxf(l0, l1), fmaxf(l2, l3));
        float se = expf(l0 - m) + expf(l1 - m) + expf(l2 - m) + expf(l3 - m);
        float lse = m + logf(se);
        float4 o = make_float4(l0 - lse, l1 - lse, l2 - lse, l3 - lse);
        ((float4*)out)[warp] = o;
    }
}

// ---------------- launch ----------------
extern "C" void kernel_launch(void* const* d_in, const int* in_sizes, int n_in,
                              void* d_out, int out_size)
{
    const float* sentence = (const float*)d_in[0];
    const float* sru_W    = (const float*)d_in[1];
    const float* sru_v    = (const float*)d_in[2];
    const float* sru_b    = (const float*)d_in[3];
    const float* ln_g     = (const float*)d_in[4];
    const float* ln_b     = (const float*)d_in[5];
    const float* W1       = (const float*)d_in[6];
    const float* b1       = (const float*)d_in[7];
    const float* bn_g     = (const float*)d_in[8];
    const float* bn_b     = (const float*)d_in[9];
    const float* bn_mean  = (const float*)d_in[10];
    const float* bn_var   = (const float*)d_in[11];
    const float* W2       = (const float*)d_in[12];
    const float* b2       = (const float*)d_in[13];
    float* out = (float*)d_out;

    __half *xl, *U, *x, *Wr, *W1r;
    cudaGetSymbolAddress((void**)&xl,  g_xl);
    cudaGetSymbolAddress((void**)&U,   g_U);
    cudaGetSymbolAddress((void**)&x,   g_x);
    cudaGetSymbolAddress((void**)&Wr,  g_Wr);
    cudaGetSymbolAddress((void**)&W1r, g_W1r);

    cudaFuncSetAttribute(gemm_fp16, cudaFuncAttributeMaxDynamicSharedMemorySize, GEMM_SMEM);

    const int M = MROWS;
    const int mtiles = (M + BM - 1) / BM;        // 782
    dim3 gemm_grid_layer(2048 / BN, mtiles);     // (16, 782)
    dim3 gemm_grid_head(EE / BN, mtiles);        // (4, 782)
    int ln_blocks = (M * 32 + 255) / 256;        // 12500
    int scan_blocks = (2 * BB * DD + 255) / 256; // 2000

    // transpose + fp16-round weights (sru_W gate-interleaved; W1 plain)
    transpose_half<<<dim3(1024 / 32, EE / 32, LL * 2), 256>>>(sru_W, Wr, EE, 1024, 1);
    transpose_half<<<dim3(EE / 32, EE / 32, 1), 256>>>(W1, W1r, EE, EE, 0);

    for (int l = 0; l < LL; l++) {
        if (l == 0)
            ln_f32<<<ln_blocks, 256>>>(sentence, ln_g, ln_b, xl, M);
        else
            ln_f16<<<ln_blocks, 256>>>(x, ln_g + l * EE, ln_b + l * EE, xl, M);
        gemm_fp16<<<gemm_grid_layer, 128, GEMM_SMEM>>>(
            xl, Wr + (size_t)l * 2 * 1024 * EE, nullptr, U,
            M, 2048, 10, (long long)1024 * EE);
        sru_scan<<<scan_blocks, 256>>>(U, sru_v + l * 4 * DD, sru_b + l * 4 * DD, x);
    }
    // head GEMM: h = x @ W1 + b1 -> xl
    gemm_fp16<<<gemm_grid_head, 128, GEMM_SMEM>>>(
        x, W1r, b1, xl, M, EE, 30, 0LL);
    head_kernel<<<ln_blocks, 256>>>(xl, bn_g, bn_b, bn_mean, bn_var, W2, b2, out, M);
}